// round 5
// baseline (speedup 1.0000x reference)
#include <cuda_runtime.h>
#include <cuda_bf16.h>
#include <cstddef>

// Problem constants
#define PB  8       // batch
#define PC  512     // channels
#define PM  64      // key dim
#define PNC 19      // out channels
#define PN  4096    // H*W

#define NTILES 512          // 8 b x 64 n-tiles (64 columns each), grid == NTILES
#define SSTRIDE 1284        // 64 c * 20 o + 4 pad floats per slice (16B bank skew)

// ---------------------------------------------------------------------------
// Scratch (only touched when gamma != 0)
// ---------------------------------------------------------------------------
__device__ float g_ctx[PB * PC * PN];  // [b][c][n]  64 MB

// ---------------------------------------------------------------------------
// Packed f32x2 helpers (sm_100+)
// ---------------------------------------------------------------------------
__device__ __forceinline__ void fma2(unsigned long long& d,
                                     unsigned long long a,
                                     unsigned long long b) {
    asm("fma.rn.f32x2 %0, %1, %2, %0;" : "+l"(d) : "l"(a), "l"(b));
}
__device__ __forceinline__ unsigned long long add2(unsigned long long a,
                                                   unsigned long long b) {
    unsigned long long r;
    asm("add.rn.f32x2 %0, %1, %2;" : "=l"(r) : "l"(a), "l"(b));
    return r;
}
__device__ __forceinline__ unsigned long long pack2(float x, float y) {
    unsigned long long r;
    asm("mov.b64 %0, {%1, %2};" : "=l"(r) : "f"(x), "f"(y));
    return r;
}
__device__ __forceinline__ float2 unpack2(unsigned long long v) {
    float2 f;
    asm("mov.b64 {%0, %1}, %2;" : "=f"(f.x), "=f"(f.y) : "l"(v));
    return f;
}

// ---------------------------------------------------------------------------
// Fused PAM kernel.
//   score[b,o,n] = sum_c Wfc[o,c] * (gamma*ctx[b,c,n] + x[b,c,n]) + bfc[o]
//
// Grid 512 CTAs (one 64-n tile each), 256 threads = 8 warps:
//   warps 0-3: c in [0,256), warps 4-7: c in [256,512)  (warp quarter = n sub-tile)
//   lane = grp(0..3)*8 + col(0..7): 4 c-slices of 64 c inside each warp.
// Each thread: one float2 of n, 64 c, 10 f32x2 o-pair accumulators per n elem.
// Reduction: shfl.bfly xor 8,16 (4 slices) then 5KB smem combine of the two
// warp halves. Weights staged once per CTA as 8 slices [64 c][20 o] + 16B skew.
// gamma != 0: block-local exact attention recompute (correctness fallback,
// never executes for the provided inputs).
// ---------------------------------------------------------------------------
__global__ void __launch_bounds__(256, 3)
pam_kernel(const float* __restrict__ x,
           const float* __restrict__ Wq,
           const float* __restrict__ bq,
           const float* __restrict__ Wk,
           const float* __restrict__ bk,
           const float* __restrict__ gamma,
           const float* __restrict__ Wfc,
           const float* __restrict__ bfc,
           float* __restrict__ out) {
    __shared__ float ws[8 * SSTRIDE];        // 41088 B
    __shared__ float2 cbuf[4][16][10];       //  5120 B

    const int tid = threadIdx.x;
    const int t = blockIdx.x;
    const int b = t >> 6;
    const int nbase = (t & 63) * 64;
    const float g = __ldg(gamma);

    // ---------------- gamma != 0 fallback (block-local, never runs here) ----
    if (g != 0.0f) {
        float* q_s  = ws;            // [64 cols][64 m] = 16 KB (overlays ws)
        float* rmax = ws + 4096;     // [64]
        float* rsum = ws + 4160;     // [64]
        float* k_s  = ws + 4224;     // [64]
        float* w_s  = ws + 4288;     // [64]
        const float* xb0 = x + (size_t)b * PC * PN;
        for (int idx = tid; idx < 64 * 64; idx += 256) {
            int j = idx >> 6, m = idx & 63;
            float a = bq[m];
            for (int c = 0; c < PC; ++c)
                a = fmaf(Wq[m * PC + c], xb0[(size_t)c * PN + nbase + j], a);
            q_s[j * 64 + m] = a;
        }
        if (tid < 64) { rmax[tid] = -3.4e38f; rsum[tid] = 0.0f; }
        __syncthreads();
        for (int p = 0; p < PN; ++p) {          // pass 1: softmax stats
            if (tid < 64) {
                float a = bk[tid];
                for (int c = 0; c < PC; ++c)
                    a = fmaf(Wk[tid * PC + c], xb0[(size_t)c * PN + p], a);
                k_s[tid] = a;
            }
            __syncthreads();
            if (tid < 64) {
                float s = 0.0f;
                for (int m = 0; m < 64; ++m)
                    s = fmaf(q_s[tid * 64 + m], k_s[m], s);
                s *= 0.125f;
                float nm = fmaxf(rmax[tid], s);
                rsum[tid] = rsum[tid] * expf(rmax[tid] - nm) + expf(s - nm);
                rmax[tid] = nm;
            }
            __syncthreads();
        }
        for (int idx = tid; idx < PC * 64; idx += 256) {
            int c = idx >> 6, j = idx & 63;
            g_ctx[(size_t)(b * PC + c) * PN + nbase + j] = 0.0f;
        }
        __syncthreads();
        for (int p = 0; p < PN; ++p) {          // pass 2: accumulate ctx
            if (tid < 64) {
                float a = bk[tid];
                for (int c = 0; c < PC; ++c)
                    a = fmaf(Wk[tid * PC + c], xb0[(size_t)c * PN + p], a);
                k_s[tid] = a;
            }
            __syncthreads();
            if (tid < 64) {
                float s = 0.0f;
                for (int m = 0; m < 64; ++m)
                    s = fmaf(q_s[tid * 64 + m], k_s[m], s);
                s *= 0.125f;
                w_s[tid] = expf(s - rmax[tid]) / rsum[tid];
            }
            __syncthreads();
            for (int idx = tid; idx < PC * 64; idx += 256) {
                int c = idx >> 6, j = idx & 63;
                g_ctx[(size_t)(b * PC + c) * PN + nbase + j] +=
                    w_s[j] * xb0[(size_t)c * PN + p];
            }
            __syncthreads();
        }
        __syncthreads();
    }

    // ---------------- stage weights: ws[slice][c_local][20], 16B skew ------
    for (int i = tid; i < PNC * PC; i += 256) {
        int o = i >> 9;
        int c = i & (PC - 1);
        ws[(c >> 6) * SSTRIDE + (c & 63) * 20 + o] = __ldg(Wfc + i);
    }
    for (int c = tid; c < PC; c += 256)
        ws[(c >> 6) * SSTRIDE + (c & 63) * 20 + 19] = 0.0f;
    __syncthreads();

    // ---------------- main accumulation ------------------------------------
    const int lane = tid & 31;
    const int wid = tid >> 5;
    const int wq = wid & 3;      // n sub-tile 0..3
    const int half = wid >> 2;   // c-half 0..1
    const int col = lane & 7;    // float2 column within warp
    const int grp = lane >> 3;   // c-slice within half (0..3)
    const int slice = half * 4 + grp;       // 0..7, 64 c each
    const int nn = nbase + wq * 16 + col * 2;

    const float* xp = x + ((size_t)b * PC + slice * 64) * PN + nn;
    const float* cp = g_ctx + ((size_t)b * PC + slice * 64) * PN + nn;
    const float* wsp = ws + slice * SSTRIDE;

    unsigned long long accA[10], accB[10];
#pragma unroll
    for (int j = 0; j < 10; ++j) { accA[j] = 0ull; accB[j] = 0ull; }

    if (g == 0.0f) {
#pragma unroll 4
        for (int c = 0; c < 64; ++c) {
            float2 xv = __ldg((const float2*)(xp + (size_t)c * PN));
            unsigned long long xa = pack2(xv.x, xv.x);
            unsigned long long xb = pack2(xv.y, xv.y);
            const ulonglong2* wr = (const ulonglong2*)(wsp + c * 20);
            ulonglong2 w0 = wr[0], w1 = wr[1], w2 = wr[2], w3 = wr[3], w4 = wr[4];
            fma2(accA[0], xa, w0.x); fma2(accB[0], xb, w0.x);
            fma2(accA[1], xa, w0.y); fma2(accB[1], xb, w0.y);
            fma2(accA[2], xa, w1.x); fma2(accB[2], xb, w1.x);
            fma2(accA[3], xa, w1.y); fma2(accB[3], xb, w1.y);
            fma2(accA[4], xa, w2.x); fma2(accB[4], xb, w2.x);
            fma2(accA[5], xa, w2.y); fma2(accB[5], xb, w2.y);
            fma2(accA[6], xa, w3.x); fma2(accB[6], xb, w3.x);
            fma2(accA[7], xa, w3.y); fma2(accB[7], xb, w3.y);
            fma2(accA[8], xa, w4.x); fma2(accB[8], xb, w4.x);
            fma2(accA[9], xa, w4.y); fma2(accB[9], xb, w4.y);
        }
    } else {
#pragma unroll 4
        for (int c = 0; c < 64; ++c) {
            float2 xv = __ldg((const float2*)(xp + (size_t)c * PN));
            float2 cv = __ldg((const float2*)(cp + (size_t)c * PN));
            xv.x = fmaf(g, cv.x, xv.x);
            xv.y = fmaf(g, cv.y, xv.y);
            unsigned long long xa = pack2(xv.x, xv.x);
            unsigned long long xb = pack2(xv.y, xv.y);
            const ulonglong2* wr = (const ulonglong2*)(wsp + c * 20);
            ulonglong2 w0 = wr[0], w1 = wr[1], w2 = wr[2], w3 = wr[3], w4 = wr[4];
            fma2(accA[0], xa, w0.x); fma2(accB[0], xb, w0.x);
            fma2(accA[1], xa, w0.y); fma2(accB[1], xb, w0.y);
            fma2(accA[2], xa, w1.x); fma2(accB[2], xb, w1.x);
            fma2(accA[3], xa, w1.y); fma2(accB[3], xb, w1.y);
            fma2(accA[4], xa, w2.x); fma2(accB[4], xb, w2.x);
            fma2(accA[5], xa, w2.y); fma2(accB[5], xb, w2.y);
            fma2(accA[6], xa, w3.x); fma2(accB[6], xb, w3.x);
            fma2(accA[7], xa, w3.y); fma2(accB[7], xb, w3.y);
            fma2(accA[8], xa, w4.x); fma2(accB[8], xb, w4.x);
            fma2(accA[9], xa, w4.y); fma2(accB[9], xb, w4.y);
        }
    }

    // ---------------- in-warp reduction over the 4 c-slices (xor 8, 16) ----
#pragma unroll
    for (int j = 0; j < 10; ++j) {
        accA[j] = add2(accA[j], __shfl_xor_sync(0xffffffffu, accA[j], 8));
        accA[j] = add2(accA[j], __shfl_xor_sync(0xffffffffu, accA[j], 16));
        accB[j] = add2(accB[j], __shfl_xor_sync(0xffffffffu, accB[j], 8));
        accB[j] = add2(accB[j], __shfl_xor_sync(0xffffffffu, accB[j], 16));
    }

    // ---------------- combine the two c-halves via smem --------------------
    // lanes grp 0/1 carry the final values: grp0 -> accA (n = col*2),
    // grp1 -> accB (n = col*2+1); slot index = grp*8+col in 0..15.
    if (half == 1 && grp < 2) {
        const int sl = grp * 8 + col;
#pragma unroll
        for (int j = 0; j < 10; ++j)
            cbuf[wq][sl][j] = unpack2(grp == 0 ? accA[j] : accB[j]);
    }
    __syncthreads();
    if (half == 0 && grp < 2) {
        const int sl = grp * 8 + col;
        const int ns = nn + grp;
        float* op = out + ((size_t)b * PNC) * PN + ns;
#pragma unroll
        for (int j = 0; j < 10; ++j) {
            float2 v = unpack2(grp == 0 ? accA[j] : accB[j]);
            float2 w = cbuf[wq][sl][j];
            op[(size_t)(2 * j) * PN] = v.x + w.x + __ldg(bfc + 2 * j);
            if (2 * j + 1 < PNC)
                op[(size_t)(2 * j + 1) * PN] = v.y + w.y + __ldg(bfc + 2 * j + 1);
        }
    }
}

// ---------------------------------------------------------------------------
// launch
// ---------------------------------------------------------------------------
extern "C" void kernel_launch(void* const* d_in, const int* in_sizes, int n_in,
                              void* d_out, int out_size) {
    const float* x     = (const float*)d_in[0];
    const float* Wq    = (const float*)d_in[1];
    const float* bq    = (const float*)d_in[2];
    const float* Wk    = (const float*)d_in[3];
    const float* bk    = (const float*)d_in[4];
    const float* gamma = (const float*)d_in[5];
    const float* Wfc   = (const float*)d_in[6];
    const float* bfc   = (const float*)d_in[7];
    float* out = (float*)d_out;

    pam_kernel<<<NTILES, 256>>>(x, Wq, bq, Wk, bk, gamma, Wfc, bfc, out);
}